// round 16
// baseline (speedup 1.0000x reference)
#include <cuda_runtime.h>
#include <stdint.h>

#define R 512
#define K 81
#define IMW_M1 1332.0f
#define IMH_M1 799.0f
#define XCLIP 4.135166556742356f   // log(1000/16)
#define SCORE_THRESH 0.001f
#define POST_NMS_TOPN 300
#define MAX_PER_IMG 100

#define KTILES 136                   // per-class 32x32 tiles (incl. diagonal)
#define TOTTILES (K * KTILES)        // 11016
#define MASK_BLOCKS 148

// scratch (no allocations allowed)
__device__ float4 g_sbox[K * R];              // sorted boxes (x1, y1, x2+1, y2+1)
__device__ float  g_sarea[K * R];             // sorted areas
__device__ unsigned long long g_keys[K * R];  // sorted keys (~score)<<32 | orig
__device__ uint32_t g_mask[K * 16 * R];       // suppression words, layout [c][w][i]
__device__ unsigned long long g_rmax[R];      // per-roi packed (score<<32 | 255-class)

// ---------------------------------------------------------------------------
// box decode for (roi r, class c), matching reference arithmetic order
// ---------------------------------------------------------------------------
__device__ __forceinline__ float4 decode_box(const float* __restrict__ rois,
                                             const float* __restrict__ deltas,
                                             int r, int c) {
    float4 roi = ((const float4*)rois)[r];
    float4 d = *(const float4*)(deltas + r * (4 * K) + c * 4);   // 16B aligned

    float w = roi.z - roi.x + 1.0f;
    float h = roi.w - roi.y + 1.0f;
    float cx = roi.x + 0.5f * w;
    float cy = roi.y + 0.5f * h;

    float dx = d.x / 10.0f;
    float dy = d.y / 10.0f;
    float dw = fminf(d.z / 5.0f, XCLIP);
    float dh = fminf(d.w / 5.0f, XCLIP);

    float pcx = dx * w + cx;
    float pcy = dy * h + cy;
    float pw = expf(dw) * w;
    float ph = expf(dh) * h;

    float4 o;
    o.x = fminf(fmaxf(pcx - 0.5f * pw, 0.0f), IMW_M1);
    o.y = fminf(fmaxf(pcy - 0.5f * ph, 0.0f), IMH_M1);
    o.z = fminf(fmaxf(pcx + 0.5f * pw - 1.0f, 0.0f), IMW_M1);
    o.w = fminf(fmaxf(pcy + 0.5f * ph - 1.0f, 0.0f), IMH_M1);
    return o;
}

// ---------------------------------------------------------------------------
// Hybrid bitonic sort of 512 u64 keys (ascending), 1 elem/thread, tid in [0,512).
// PROVEN ONLY inside 1024-thread blocks (R8-R10/R14). Used only in K1.
// ---------------------------------------------------------------------------
__device__ __forceinline__ unsigned long long hybrid_sort512(
    unsigned long long key, int tid,
    unsigned long long* __restrict__ bufA,
    unsigned long long* __restrict__ bufB)
{
    const int lane = tid & 31;
    #pragma unroll
    for (int k2 = 2; k2 <= 32; k2 <<= 1) {
        #pragma unroll
        for (int j = k2 >> 1; j > 0; j >>= 1) {
            bool up = ((tid & k2) == 0);
            bool amLow = ((lane & j) == 0);
            unsigned long long pk = __shfl_xor_sync(0xFFFFFFFFu, key, j);
            bool keepMin = (up == amLow);
            bool take = keepMin ? (pk < key) : (pk > key);
            if (take) key = pk;
        }
    }
    int par = 0;
    #pragma unroll
    for (int k2 = 64; k2 <= 512; k2 <<= 1) {
        bool up = ((tid & k2) == 0);
        #pragma unroll
        for (int j = k2 >> 1; j >= 32; j >>= 1) {
            unsigned long long* buf = par ? bufB : bufA;
            buf[tid] = key;
            asm volatile("bar.sync 1, 512;" ::: "memory");
            unsigned long long pk = buf[tid ^ j];
            bool amLow = ((tid & j) == 0);
            bool keepMin = (up == amLow);
            bool take = keepMin ? (pk < key) : (pk > key);
            if (take) key = pk;
            par ^= 1;
        }
        #pragma unroll
        for (int j = 16; j > 0; j >>= 1) {
            bool amLow = ((lane & j) == 0);
            unsigned long long pk = __shfl_xor_sync(0xFFFFFFFFu, key, j);
            bool keepMin = (up == amLow);
            bool take = keepMin ? (pk < key) : (pk > key);
            if (take) key = pk;
        }
    }
    return key;
}

// ---------------------------------------------------------------------------
// K1: per-class sort + decode; publish sorted boxes/areas/keys to global.
// 1024 threads (sort in proven environment).
// ---------------------------------------------------------------------------
__global__ void __launch_bounds__(1024, 1)
sort_kernel(const float* __restrict__ rois,
            const float* __restrict__ deltas,
            const float* __restrict__ scores) {
    __shared__ unsigned long long scratch[1024];   // sort double-buffer
    __shared__ float4 sbox[R];                     // boxes by original index

    const int c = blockIdx.x;
    const int tid = threadIdx.x;
    const int wid = tid >> 5;

    unsigned long long key = 0;
    if (wid < 16) {
        // key: descending score, ascending original index (softmax scores > 0)
        float s = scores[tid * K + c];
        key = (((unsigned long long)(~__float_as_uint(s))) << 32) | (uint32_t)tid;
        key = hybrid_sort512(key, tid, scratch, scratch + 512);
    } else {
        int t = tid - 512;
        sbox[t] = decode_box(rois, deltas, t, c);
    }
    __syncthreads();

    if (wid < 16) {
        int orig = (int)(key & 0xFFFFFFFFull);
        float4 b4 = sbox[orig];
        g_keys[c * R + tid] = key;
        // area in reference expression order; store pre-incremented coords
        g_sarea[c * R + tid] = (b4.z - b4.x + 1.0f) * (b4.w - b4.y + 1.0f);
        g_sbox[c * R + tid] = make_float4(b4.x, b4.y, b4.z + 1.0f, b4.w + 1.0f);
    }
}

// ---------------------------------------------------------------------------
// K2: mask build over the full chip. Tile t in [0, 11016): class = t/136,
// per-class tile tt -> (rc, w) via the proven subtractive map; proven
// lane==ii scatter store.
// ---------------------------------------------------------------------------
__global__ void __launch_bounds__(1024, 1)
mask_kernel() {
    const int b = blockIdx.x;
    const int wid = threadIdx.x >> 5;
    const int lane = threadIdx.x & 31;

    int start = (b * TOTTILES) / MASK_BLOCKS;
    int end   = ((b + 1) * TOTTILES) / MASK_BLOCKS;

    for (int t = start + wid; t < end; t += 32) {
        int c  = t / KTILES;
        int tt = t - c * KTILES;
        int rc = 0;
        while (tt >= 16 - rc) { tt -= 16 - rc; rc++; }
        int w = rc + tt;

        int base = c * R;
        int jcol = (w << 5) + lane;
        float4 cb = g_sbox[base + jcol];
        float nca = -g_sarea[base + jcol];
        int i0 = rc << 5;
        bool diag = (w == rc);

        uint32_t* mrow = g_mask + (c * 16 + w) * R + i0;
        #pragma unroll 8
        for (int ii = 0; ii < 32; ii++) {
            int i = i0 + ii;
            float4 rb = g_sbox[base + i];       // broadcast, L1-hot
            float ra = g_sarea[base + i];
            float iw = fminf(cb.z, rb.z) - fmaxf(cb.x, rb.x);
            float ih = fminf(cb.w, rb.w) - fmaxf(cb.y, rb.y);
            float inter = fmaxf(iw, 0.0f) * fmaxf(ih, 0.0f);
            // iou > 0.5  <=>  3*inter > ra + ca
            bool sup = (fmaf(3.0f, inter, nca) > ra);
            if (diag) sup = sup && (jcol > i);
            uint32_t word = __ballot_sync(0xFFFFFFFFu, sup);
            if (lane == ii) mrow[ii] = word;
        }
    }
}

// ---------------------------------------------------------------------------
// K3: per-class greedy suppression + per-roi class-max atomicMax.
// ---------------------------------------------------------------------------
__global__ void __launch_bounds__(512, 1)
greedy_kernel() {
    __shared__ uint32_t smask[R * 16];
    __shared__ uint32_t skeep[16];

    const int c = blockIdx.x;
    const int tid = threadIdx.x;
    const int wid = tid >> 5;
    const int lane = tid & 31;

    // load triangle (coalesced across tid per word); zero below diagonal
    {
        int rc = tid >> 5;
        #pragma unroll
        for (int w = 0; w < 16; w++) {
            smask[tid * 16 + w] =
                (w < rc) ? 0u : g_mask[(c * 16 + w) * R + tid];
        }
    }
    __syncthreads();

    // greedy: warp 0, lane-replicated current word (R8-R10-proven logic)
    if (wid == 0) {
        uint32_t remw = 0;              // lane l (&15) owns removed word l&15
        const int lw = lane & 15;
        int kept = 0;
        #pragma unroll 1
        for (int ow = 0; ow < 16; ow++) {
            uint32_t cur = __shfl_sync(0xFFFFFFFFu, remw, ow);
            uint32_t mo[32];
            #pragma unroll
            for (int b = 0; b < 32; b++) mo[b] = smask[(ow * 32 + b) * 16 + ow];
            uint32_t kcur = 0;
            #pragma unroll
            for (int b = 0; b < 32; b++) {
                uint32_t ml = smask[(ow * 32 + b) * 16 + lw];
                if (!((cur >> b) & 1u)) {
                    kept++;
                    cur  |= mo[b];
                    remw |= ml;
                    if (kept <= POST_NMS_TOPN) kcur |= (1u << b);
                }
            }
            if (lane == 0) skeep[ow] = kcur;
        }
    }
    __syncthreads();

    // per-roi class-max via packed atomicMax (proven)
    unsigned long long key = g_keys[c * R + tid];
    unsigned long long k0  = g_keys[c * R];
    float topScore = __uint_as_float(~(uint32_t)(k0 >> 32));
    bool cvalid = (c != 0) && (topScore > SCORE_THRESH);
    bool kp = (skeep[tid >> 5] >> (tid & 31)) & 1u;
    if (kp && cvalid) {
        int orig = (int)(key & 0xFFFFFFFFull);
        uint32_t bits = ~(uint32_t)(key >> 32);
        unsigned long long pkey =
            (((unsigned long long)bits) << 32) | (unsigned int)(255 - c);
        atomicMax(&g_rmax[orig], pkey);
    }
}

// ---------------------------------------------------------------------------
// K4: tail — R14-PROVEN verbatim (512 threads, shared bitonic, plain reads).
// ---------------------------------------------------------------------------
__global__ void __launch_bounds__(512, 1)
tail_kernel(const float* __restrict__ rois,
            const float* __restrict__ deltas,
            float* __restrict__ out, int out_size) {
    __shared__ unsigned long long skeys[R];
    __shared__ int slabel[R];
    const int tid = threadIdx.x;

    // zero full output (poisoned by harness)
    for (int i = tid; i < out_size; i += 512) out[i] = 0.0f;

    // plain read + reset (element tid touched only by thread tid; replay-safe)
    unsigned long long v = g_rmax[tid];
    g_rmax[tid] = 0ull;
    uint32_t bits = (uint32_t)(v >> 32);            // 0 if nothing kept
    int lbl = (v != 0ull) ? (255 - (int)(v & 0xFFull)) : 0;
    slabel[tid] = lbl;
    skeys[tid] = (((unsigned long long)(~bits)) << 32) | (uint32_t)tid;
    __syncthreads();

    // shared-memory bitonic sort (ascending: score desc, idx asc)
    for (int k2 = 2; k2 <= R; k2 <<= 1) {
        for (int j = k2 >> 1; j > 0; j >>= 1) {
            int ixj = tid ^ j;
            if (ixj > tid) {
                bool up = ((tid & k2) == 0);
                unsigned long long a = skeys[tid], b = skeys[ixj];
                if ((a > b) == up) { skeys[tid] = b; skeys[ixj] = a; }
            }
            __syncthreads();
        }
    }

    if (tid < MAX_PER_IMG) {
        unsigned long long kk = skeys[tid];
        int r = (int)(kk & 0xFFFFFFFFull);
        float sc = __uint_as_float(~(uint32_t)(kk >> 32));
        int lbl2 = slabel[r];
        bool valid = sc > SCORE_THRESH;
        float4 bb = decode_box(rois, deltas, r, lbl2);

        if (out_size >= 5 * MAX_PER_IMG) {
            out[tid * 5 + 0] = valid ? sc : 0.0f;
            out[tid * 5 + 1] = valid ? bb.x : 0.0f;
            out[tid * 5 + 2] = valid ? bb.y : 0.0f;
            out[tid * 5 + 3] = valid ? bb.z : 0.0f;
            out[tid * 5 + 4] = valid ? bb.w : 0.0f;
        }
        if (out_size >= 6 * MAX_PER_IMG) out[5 * MAX_PER_IMG + tid] = (float)lbl2;
        if (out_size >= 7 * MAX_PER_IMG) out[6 * MAX_PER_IMG + tid] = (float)r;
    }
}

// ---------------------------------------------------------------------------
extern "C" void kernel_launch(void* const* d_in, const int* in_sizes, int n_in,
                              void* d_out, int out_size) {
    const float* rois   = (const float*)d_in[0];
    const float* deltas = (const float*)d_in[1];
    const float* scores = (const float*)d_in[2];
    float* out = (float*)d_out;

    sort_kernel<<<K, 1024>>>(rois, deltas, scores);
    mask_kernel<<<MASK_BLOCKS, 1024>>>();
    greedy_kernel<<<K, 512>>>();
    tail_kernel<<<1, 512>>>(rois, deltas, out, out_size);
}